// round 6
// baseline (speedup 1.0000x reference)
#include <cuda_runtime.h>
#include <cuda_bf16.h>
#include <cstdint>

// Problem constants
#define Bsz   2
#define Sseq  2048
#define Dm    1024
#define Hh    16
#define DKh   64
#define Mrows (Bsz * Sseq)   // 4096

typedef __nv_bfloat16 bf;

// ---- scratch (__device__ globals; no allocation allowed) ----
__device__ bf g_xqh[Mrows * Dm], g_xql[Mrows * Dm];
__device__ bf g_xkh[Mrows * Dm], g_xkl[Mrows * Dm];
__device__ bf g_xvh[Mrows * Dm], g_xvl[Mrows * Dm];
__device__ bf g_wqh[Dm * Dm], g_wql[Dm * Dm];
__device__ bf g_wkh[Dm * Dm], g_wkl[Dm * Dm];
__device__ bf g_wvh[Dm * Dm], g_wvl[Dm * Dm];
__device__ bf g_woh[Dm * Dm], g_wol[Dm * Dm];
__device__ bf g_Qh[Mrows * Dm], g_Ql[Mrows * Dm];
__device__ bf g_Kh[Mrows * Dm], g_Kl[Mrows * Dm];
__device__ bf g_Vth[Mrows * Dm], g_Vtl[Mrows * Dm];  // [b][h][d][s]
__device__ bf g_Ctxh[Mrows * Dm], g_Ctxl[Mrows * Dm];

// ===========================================================================
// helpers
// ===========================================================================
__device__ __forceinline__ void mma16816(float* c, const uint32_t* a, uint32_t b0, uint32_t b1)
{
    asm volatile(
        "mma.sync.aligned.m16n8k16.row.col.f32.bf16.bf16.f32 "
        "{%0,%1,%2,%3}, {%4,%5,%6,%7}, {%8,%9}, {%0,%1,%2,%3};\n"
        : "+f"(c[0]), "+f"(c[1]), "+f"(c[2]), "+f"(c[3])
        : "r"(a[0]), "r"(a[1]), "r"(a[2]), "r"(a[3]), "r"(b0), "r"(b1));
}

__device__ __forceinline__ void ldsm4(uint32_t& r0, uint32_t& r1, uint32_t& r2, uint32_t& r3,
                                      uint32_t addr)
{
    asm volatile("ldmatrix.sync.aligned.m8n8.x4.shared.b16 {%0,%1,%2,%3}, [%4];\n"
                 : "=r"(r0), "=r"(r1), "=r"(r2), "=r"(r3) : "r"(addr));
}

__device__ __forceinline__ void split2(float x, float y, uint32_t& hi, uint32_t& lo)
{
    bf hx = __float2bfloat16(x), hy = __float2bfloat16(y);
    bf lx = __float2bfloat16(x - __bfloat162float(hx));
    bf ly = __float2bfloat16(y - __bfloat162float(hy));
    __nv_bfloat162 h(hx, hy), l(lx, ly);
    hi = *(uint32_t*)&h; lo = *(uint32_t*)&l;
}

__device__ __forceinline__ uint32_t smem_u32(const void* p)
{
    uint32_t a;
    asm("{ .reg .u64 t; cvta.to.shared.u64 t, %1; cvt.u32.u64 %0, t; }" : "=r"(a) : "l"(p));
    return a;
}
__device__ __forceinline__ void cp16(uint32_t dst, const void* src)
{
    asm volatile("cp.async.ca.shared.global [%0], [%1], 16;\n" :: "r"(dst), "l"(src));
}
#define CP_COMMIT() asm volatile("cp.async.commit_group;\n" ::: "memory")
#define CP_WAIT(n)  asm volatile("cp.async.wait_group %0;\n" :: "n"(n) : "memory")

// ===========================================================================
// pre-split: fp32 -> bf16 hi/lo
// ===========================================================================
__global__ __launch_bounds__(256)
void split_all(const float* q, const float* k, const float* v,
               const float* wq, const float* wk, const float* wv, const float* wo)
{
    const int z = blockIdx.y;
    const float* src; bf *hi, *lo; int n;
    switch (z) {
        case 0: src = q;  hi = g_xqh; lo = g_xql; n = Mrows * Dm; break;
        case 1: src = k;  hi = g_xkh; lo = g_xkl; n = Mrows * Dm; break;
        case 2: src = v;  hi = g_xvh; lo = g_xvl; n = Mrows * Dm; break;
        case 3: src = wq; hi = g_wqh; lo = g_wql; n = Dm * Dm;    break;
        case 4: src = wk; hi = g_wkh; lo = g_wkl; n = Dm * Dm;    break;
        case 5: src = wv; hi = g_wvh; lo = g_wvl; n = Dm * Dm;    break;
        default: src = wo; hi = g_woh; lo = g_wol; n = Dm * Dm;   break;
    }
    const int t = blockIdx.x * 256 + threadIdx.x;
    if (t * 4 >= n) return;
    const float4 x = ((const float4*)src)[t];
    uint32_t h0, l0, h1, l1;
    split2(x.x, x.y, h0, l0);
    split2(x.z, x.w, h1, l1);
    ((uint2*)hi)[t] = make_uint2(h0, h1);
    ((uint2*)lo)[t] = make_uint2(l0, l1);
}

// ===========================================================================
// Unified tensor-core GEMM (pre-split bf16), ldmatrix fragment loads.
// z: 0=Q  1=K  2=V(transposed out)  3=O(fp32 out)
// ===========================================================================
#define GBK 32
#define GST 40
#define ARR_E (128 * GST)
#define STG_E (4 * ARR_E)
#define STG_B (STG_E * 2)
#define SMEM_TOT (2 * STG_B)   // 81920 B

__global__ __launch_bounds__(256, 2)
void gemm_all(int zbase,
              const float* __restrict__ bq, const float* __restrict__ bk,
              const float* __restrict__ bv, const float* __restrict__ bo,
              float* __restrict__ out)
{
    extern __shared__ bf dsm[];
    const uint32_t sbase = smem_u32(dsm);

    const int z = blockIdx.z + zbase;
    const bf *Ah, *Al, *Wh, *Wl;
    const float* bias;
    bf *Oh = nullptr, *Ol = nullptr;
    float* Cf = nullptr;
    int mode; float qscale = 1.0f;
    switch (z) {
        case 0:  Ah = g_xqh; Al = g_xql; Wh = g_wqh; Wl = g_wql; bias = bq;
                 Oh = g_Qh; Ol = g_Ql; mode = 0; qscale = 0.125f; break;
        case 1:  Ah = g_xkh; Al = g_xkl; Wh = g_wkh; Wl = g_wkl; bias = bk;
                 Oh = g_Kh; Ol = g_Kl; mode = 0; break;
        case 2:  Ah = g_xvh; Al = g_xvl; Wh = g_wvh; Wl = g_wvl; bias = bv;
                 Oh = g_Vth; Ol = g_Vtl; mode = 2; break;
        default: Ah = g_Ctxh; Al = g_Ctxl; Wh = g_woh; Wl = g_wol; bias = bo;
                 Cf = out; mode = 3; break;
    }

    const int tid  = threadIdx.x;
    const int lane = tid & 31;
    const int warp = tid >> 5;
    const int wm   = warp & 3;
    const int wn   = warp >> 2;
    const int gg8  = lane >> 2;
    const int tg   = lane & 3;
    const int bM   = blockIdx.y * 128;
    const int bN   = blockIdx.x * 128;
    const int K    = Dm, N = Dm;

    // ldmatrix per-lane offsets
    const int lA_row = (lane & 7) + ((lane >> 3) & 1) * 8;  // + tile row base
    const int lA_col = (lane >> 4) * 8;                      // + ks
    const int lB_row = (lane & 7) + (lane >> 4) * 8;         // + n tile base
    const int lB_col = ((lane >> 3) & 1) * 8;                // + ks

    const int lr = tid >> 1;
    const int lq = tid & 1;
    const bf* gA_h = Ah + (size_t)(bM + lr) * K + lq * 16;
    const bf* gA_l = Al + (size_t)(bM + lr) * K + lq * 16;
    const bf* gW_h = Wh + (size_t)(bN + lr) * K + lq * 16;
    const bf* gW_l = Wl + (size_t)(bN + lr) * K + lq * 16;
    const uint32_t drow = lr * (GST * 2) + lq * 32;

    float acc[2][8][4];
    #pragma unroll
    for (int i = 0; i < 2; i++)
        #pragma unroll
        for (int j = 0; j < 8; j++)
            #pragma unroll
            for (int t = 0; t < 4; t++) acc[i][j][t] = 0.f;

    const int nch = K / GBK;   // 32

    {
        const uint32_t d0 = sbase + drow;
        cp16(d0,                  gA_h);
        cp16(d0 + 16,             gA_h + 8);
        cp16(d0 + ARR_E * 2,      gA_l);
        cp16(d0 + ARR_E * 2 + 16, gA_l + 8);
        cp16(d0 + ARR_E * 4,      gW_h);
        cp16(d0 + ARR_E * 4 + 16, gW_h + 8);
        cp16(d0 + ARR_E * 6,      gW_l);
        cp16(d0 + ARR_E * 6 + 16, gW_l + 8);
        CP_COMMIT();
    }

    for (int i = 0; i < nch; i++) {
        if (i + 1 < nch) {
            const int k0 = (i + 1) * GBK;
            const uint32_t d0 = sbase + ((i + 1) & 1) * STG_B + drow;
            cp16(d0,                  gA_h + k0);
            cp16(d0 + 16,             gA_h + k0 + 8);
            cp16(d0 + ARR_E * 2,      gA_l + k0);
            cp16(d0 + ARR_E * 2 + 16, gA_l + k0 + 8);
            cp16(d0 + ARR_E * 4,      gW_h + k0);
            cp16(d0 + ARR_E * 4 + 16, gW_h + k0 + 8);
            cp16(d0 + ARR_E * 6,      gW_l + k0);
            cp16(d0 + ARR_E * 6 + 16, gW_l + k0 + 8);
            CP_COMMIT();
            CP_WAIT(1);
        } else {
            CP_WAIT(0);
        }
        __syncthreads();

        const uint32_t stg = sbase + (i & 1) * STG_B;

        #pragma unroll
        for (int ks = 0; ks < GBK; ks += 16) {
            uint32_t ah[2][4], al[2][4];
            #pragma unroll
            for (int mt = 0; mt < 2; mt++) {
                const uint32_t ra = stg +
                    ((wm * 32 + mt * 16 + lA_row) * GST + ks + lA_col) * 2;
                ldsm4(ah[mt][0], ah[mt][1], ah[mt][2], ah[mt][3], ra);
                ldsm4(al[mt][0], al[mt][1], al[mt][2], al[mt][3], ra + ARR_E * 2);
            }
            #pragma unroll
            for (int np = 0; np < 4; np++) {
                uint32_t bh[4], bl[4];
                const uint32_t rb = stg + ARR_E * 4 +
                    ((wn * 64 + np * 16 + lB_row) * GST + ks + lB_col) * 2;
                ldsm4(bh[0], bh[1], bh[2], bh[3], rb);
                ldsm4(bl[0], bl[1], bl[2], bl[3], rb + ARR_E * 2);
                #pragma unroll
                for (int qq = 0; qq < 2; qq++) {
                    const int nt = np * 2 + qq;
                    #pragma unroll
                    for (int mt = 0; mt < 2; mt++) {
                        mma16816(acc[mt][nt], ah[mt], bh[2 * qq], bh[2 * qq + 1]);
                        mma16816(acc[mt][nt], ah[mt], bl[2 * qq], bl[2 * qq + 1]);
                        mma16816(acc[mt][nt], al[mt], bh[2 * qq], bh[2 * qq + 1]);
                    }
                }
            }
        }
        __syncthreads();
    }

    // ---- epilogue ----
    #pragma unroll
    for (int mt = 0; mt < 2; mt++) {
        #pragma unroll
        for (int nt = 0; nt < 8; nt++) {
            const int col = bN + wn * 64 + nt * 8 + 2 * tg;
            const float b0 = bias[col], b1 = bias[col + 1];
            const int r0 = bM + wm * 32 + mt * 16 + gg8;
            float v00 = acc[mt][nt][0] + b0, v01 = acc[mt][nt][1] + b1;
            float v10 = acc[mt][nt][2] + b0, v11 = acc[mt][nt][3] + b1;
            if (mode == 3) {
                *(float2*)&Cf[(size_t)r0 * N + col]       = make_float2(v00, v01);
                *(float2*)&Cf[(size_t)(r0 + 8) * N + col] = make_float2(v10, v11);
            } else if (mode == 0) {
                v00 *= qscale; v01 *= qscale; v10 *= qscale; v11 *= qscale;
                uint32_t h, l;
                split2(v00, v01, h, l);
                *(uint32_t*)&Oh[(size_t)r0 * N + col] = h;
                *(uint32_t*)&Ol[(size_t)r0 * N + col] = l;
                split2(v10, v11, h, l);
                *(uint32_t*)&Oh[(size_t)(r0 + 8) * N + col] = h;
                *(uint32_t*)&Ol[(size_t)(r0 + 8) * N + col] = l;
            } else { // mode 2: transposed per head [b][h][d][s]
                #pragma unroll
                for (int rr = 0; rr < 2; rr++) {
                    const int r  = r0 + rr * 8;
                    const int bb = r >> 11;
                    const int s  = r & 2047;
                    const float x0 = rr ? v10 : v00;
                    const float x1 = rr ? v11 : v01;
                    #pragma unroll
                    for (int cc = 0; cc < 2; cc++) {
                        const int c  = col + cc;
                        const int hh = c >> 6;
                        const int d  = c & 63;
                        const float x = cc ? x1 : x0;
                        const size_t idx = (((size_t)bb * Hh + hh) * DKh + d) * Sseq + s;
                        bf hi = __float2bfloat16(x);
                        bf lo = __float2bfloat16(x - __bfloat162float(hi));
                        Oh[idx] = hi;
                        Ol[idx] = lo;
                    }
                }
            }
        }
    }
}

// ===========================================================================
// Tensor-core flash attention with ldmatrix fragment loads.
// ===========================================================================
#define ALD 72

__global__ __launch_bounds__(128)
void attn_tc()
{
    __shared__ bf Ksh[64][ALD], Ksl[64][ALD];
    __shared__ bf Vsh[64][ALD], Vsl[64][ALD];

    const int tid  = threadIdx.x;
    const int lane = tid & 31;
    const int warp = tid >> 5;
    const int g    = lane >> 2;
    const int tg   = lane & 3;
    const int b    = blockIdx.z;
    const int h    = blockIdx.y;
    const int q0   = blockIdx.x * 64;

    // ldmatrix lane offsets (B-style tiles)
    const int lB_row = (lane & 7) + (lane >> 4) * 8;
    const int lB_col = ((lane >> 3) & 1) * 8;
    const uint32_t kh_base = smem_u32(&Ksh[0][0]);
    const uint32_t kl_base = smem_u32(&Ksl[0][0]);
    const uint32_t vh_base = smem_u32(&Vsh[0][0]);
    const uint32_t vl_base = smem_u32(&Vsl[0][0]);

    uint32_t qh[4][4], ql[4][4];
    {
        const bf* Qh = g_Qh + (size_t)(b * Sseq + q0 + warp * 16) * Dm + h * DKh;
        const bf* Ql = g_Ql + (size_t)(b * Sseq + q0 + warp * 16) * Dm + h * DKh;
        #pragma unroll
        for (int ks = 0; ks < 4; ks++) {
            const int c0 = ks * 16 + 2 * tg;
            qh[ks][0] = *(const uint32_t*)&Qh[(size_t)g * Dm + c0];
            qh[ks][1] = *(const uint32_t*)&Qh[(size_t)(g + 8) * Dm + c0];
            qh[ks][2] = *(const uint32_t*)&Qh[(size_t)g * Dm + c0 + 8];
            qh[ks][3] = *(const uint32_t*)&Qh[(size_t)(g + 8) * Dm + c0 + 8];
            ql[ks][0] = *(const uint32_t*)&Ql[(size_t)g * Dm + c0];
            ql[ks][1] = *(const uint32_t*)&Ql[(size_t)(g + 8) * Dm + c0];
            ql[ks][2] = *(const uint32_t*)&Ql[(size_t)g * Dm + c0 + 8];
            ql[ks][3] = *(const uint32_t*)&Ql[(size_t)(g + 8) * Dm + c0 + 8];
        }
    }

    float o[8][4];
    #pragma unroll
    for (int nt = 0; nt < 8; nt++)
        #pragma unroll
        for (int t = 0; t < 4; t++) o[nt][t] = 0.f;
    float m0 = -1e30f, m1 = -1e30f, l0 = 0.f, l1 = 0.f;

    const bf* Kbh = g_Kh + (size_t)b * Sseq * Dm + h * DKh;
    const bf* Kbl = g_Kl + (size_t)b * Sseq * Dm + h * DKh;
    const bf* Vbh = g_Vth + ((size_t)b * Hh + h) * DKh * Sseq;
    const bf* Vbl = g_Vtl + ((size_t)b * Hh + h) * DKh * Sseq;

    for (int kv0 = 0; kv0 < Sseq; kv0 += 64) {
        __syncthreads();
        #pragma unroll
        for (int j = 0; j < 4; j++) {
            const int idx = tid + j * 128;
            const int r = idx >> 3, c = (idx & 7) * 8;
            *(float4*)&Ksh[r][c] = *(const float4*)&Kbh[(size_t)(kv0 + r) * Dm + c];
            *(float4*)&Ksl[r][c] = *(const float4*)&Kbl[(size_t)(kv0 + r) * Dm + c];
            *(float4*)&Vsh[r][c] = *(const float4*)&Vbh[(size_t)r * Sseq + kv0 + c];
            *(float4*)&Vsl[r][c] = *(const float4*)&Vbl[(size_t)r * Sseq + kv0 + c];
        }
        __syncthreads();

        // ---- S = Q K^T ----
        float s[8][4];
        #pragma unroll
        for (int nt = 0; nt < 8; nt++)
            #pragma unroll
            for (int t = 0; t < 4; t++) s[nt][t] = 0.f;
        #pragma unroll
        for (int ks = 0; ks < 4; ks++) {
            const uint32_t coff = ((uint32_t)(ks * 16 + lB_col)) * 2;
            #pragma unroll
            for (int np = 0; np < 4; np++) {
                uint32_t bh[4], bl[4];
                const uint32_t roff = (uint32_t)((np * 16 + lB_row) * ALD) * 2 + coff;
                ldsm4(bh[0], bh[1], bh[2], bh[3], kh_base + roff);
                ldsm4(bl[0], bl[1], bl[2], bl[3], kl_base + roff);
                #pragma unroll
                for (int qq = 0; qq < 2; qq++) {
                    const int nt = np * 2 + qq;
                    mma16816(s[nt], qh[ks], bh[2 * qq], bh[2 * qq + 1]);
                    mma16816(s[nt], qh[ks], bl[2 * qq], bl[2 * qq + 1]);
                    mma16816(s[nt], ql[ks], bh[2 * qq], bh[2 * qq + 1]);
                }
            }
        }

        // ---- online softmax ----
        float mx0 = -1e30f, mx1 = -1e30f;
        #pragma unroll
        for (int nt = 0; nt < 8; nt++) {
            mx0 = fmaxf(mx0, fmaxf(s[nt][0], s[nt][1]));
            mx1 = fmaxf(mx1, fmaxf(s[nt][2], s[nt][3]));
        }
        mx0 = fmaxf(mx0, __shfl_xor_sync(0xffffffffu, mx0, 1));
        mx0 = fmaxf(mx0, __shfl_xor_sync(0xffffffffu, mx0, 2));
        mx1 = fmaxf(mx1, __shfl_xor_sync(0xffffffffu, mx1, 1));
        mx1 = fmaxf(mx1, __shfl_xor_sync(0xffffffffu, mx1, 2));
        const float nm0 = fmaxf(m0, mx0), nm1 = fmaxf(m1, mx1);
        const float sc0 = __expf(m0 - nm0), sc1 = __expf(m1 - nm1);
        m0 = nm0; m1 = nm1;
        l0 *= sc0; l1 *= sc1;
        #pragma unroll
        for (int nt = 0; nt < 8; nt++) {
            o[nt][0] *= sc0; o[nt][1] *= sc0;
            o[nt][2] *= sc1; o[nt][3] *= sc1;
        }

        // ---- P = exp(S - m); PV ----
        #pragma unroll
        for (int ks = 0; ks < 4; ks++) {
            const float e00 = __expf(s[2 * ks][0] - nm0);
            const float e01 = __expf(s[2 * ks][1] - nm0);
            const float e10 = __expf(s[2 * ks][2] - nm1);
            const float e11 = __expf(s[2 * ks][3] - nm1);
            const float f00 = __expf(s[2 * ks + 1][0] - nm0);
            const float f01 = __expf(s[2 * ks + 1][1] - nm0);
            const float f10 = __expf(s[2 * ks + 1][2] - nm1);
            const float f11 = __expf(s[2 * ks + 1][3] - nm1);
            l0 += (e00 + e01) + (f00 + f01);
            l1 += (e10 + e11) + (f10 + f11);
            uint32_t ph[4], pl[4];
            split2(e00, e01, ph[0], pl[0]);
            split2(e10, e11, ph[1], pl[1]);
            split2(f00, f01, ph[2], pl[2]);
            split2(f10, f11, ph[3], pl[3]);
            const uint32_t coff = ((uint32_t)(ks * 16 + lB_col)) * 2;
            #pragma unroll
            for (int np = 0; np < 4; np++) {
                uint32_t bh[4], bl[4];
                const uint32_t roff = (uint32_t)((np * 16 + lB_row) * ALD) * 2 + coff;
                ldsm4(bh[0], bh[1], bh[2], bh[3], vh_base + roff);
                ldsm4(bl[0], bl[1], bl[2], bl[3], vl_base + roff);
                #pragma unroll
                for (int qq = 0; qq < 2; qq++) {
                    const int nt = np * 2 + qq;
                    mma16816(o[nt], ph, bh[2 * qq], bh[2 * qq + 1]);
                    mma16816(o[nt], ph, bl[2 * qq], bl[2 * qq + 1]);
                    mma16816(o[nt], pl, bh[2 * qq], bh[2 * qq + 1]);
                }
            }
        }
    }

    l0 += __shfl_xor_sync(0xffffffffu, l0, 1);
    l0 += __shfl_xor_sync(0xffffffffu, l0, 2);
    l1 += __shfl_xor_sync(0xffffffffu, l1, 1);
    l1 += __shfl_xor_sync(0xffffffffu, l1, 2);
    const float i0 = 1.f / l0, i1 = 1.f / l1;

    bf* OpH = g_Ctxh + (size_t)(b * Sseq + q0 + warp * 16) * Dm + h * DKh;
    bf* OpL = g_Ctxl + (size_t)(b * Sseq + q0 + warp * 16) * Dm + h * DKh;
    #pragma unroll
    for (int nt = 0; nt < 8; nt++) {
        const int c = nt * 8 + 2 * tg;
        uint32_t h0, l0w, h1, l1w;
        split2(o[nt][0] * i0, o[nt][1] * i0, h0, l0w);
        split2(o[nt][2] * i1, o[nt][3] * i1, h1, l1w);
        *(uint32_t*)&OpH[(size_t)g * Dm + c]       = h0;
        *(uint32_t*)&OpL[(size_t)g * Dm + c]       = l0w;
        *(uint32_t*)&OpH[(size_t)(g + 8) * Dm + c] = h1;
        *(uint32_t*)&OpL[(size_t)(g + 8) * Dm + c] = l1w;
    }
}

// ---------------------------------------------------------------------------
// Launch
// ---------------------------------------------------------------------------
extern "C" void kernel_launch(void* const* d_in, const int* in_sizes, int n_in,
                              void* d_out, int out_size)
{
    const float* q  = (const float*)d_in[0];
    const float* k  = (const float*)d_in[1];
    const float* v  = (const float*)d_in[2];
    const float* wq = (const float*)d_in[3];
    const float* bq = (const float*)d_in[4];
    const float* wk = (const float*)d_in[5];
    const float* bk = (const float*)d_in[6];
    const float* wv = (const float*)d_in[7];
    const float* bv = (const float*)d_in[8];
    const float* wo = (const float*)d_in[9];
    const float* bo = (const float*)d_in[10];
    float* out = (float*)d_out;

    cudaFuncSetAttribute(gemm_all, cudaFuncAttributeMaxDynamicSharedMemorySize, SMEM_TOT);

    split_all<<<dim3((Mrows * Dm) / (4 * 256), 7), 256>>>(q, k, v, wq, wk, wv, wo);

    gemm_all<<<dim3(Dm / 128, Mrows / 128, 3), 256, SMEM_TOT>>>(0, bq, bk, bv, bo, out);

    attn_tc<<<dim3(Sseq / 64, Hh, Bsz), 128>>>();

    gemm_all<<<dim3(Dm / 128, Mrows / 128, 1), 256, SMEM_TOT>>>(3, bq, bk, bv, bo, out);
}

// round 8
// speedup vs baseline: 1.1408x; 1.1408x over previous
#include <cuda_runtime.h>
#include <cuda_bf16.h>
#include <cstdint>

// Problem constants
#define Bsz   2
#define Sseq  2048
#define Dm    1024
#define Hh    16
#define DKh   64
#define Mrows (Bsz * Sseq)   // 4096

typedef __nv_bfloat16 bf;

// ---- scratch (__device__ globals; no allocation allowed) ----
__device__ bf g_xqh[Mrows * Dm], g_xql[Mrows * Dm];
__device__ bf g_xkh[Mrows * Dm], g_xkl[Mrows * Dm];
__device__ bf g_xvh[Mrows * Dm], g_xvl[Mrows * Dm];
__device__ bf g_wqh[Dm * Dm], g_wql[Dm * Dm];
__device__ bf g_wkh[Dm * Dm], g_wkl[Dm * Dm];
__device__ bf g_wvh[Dm * Dm], g_wvl[Dm * Dm];
__device__ bf g_woh[Dm * Dm], g_wol[Dm * Dm];
__device__ bf g_Qh[Mrows * Dm], g_Ql[Mrows * Dm];
__device__ bf g_Kh[Mrows * Dm], g_Kl[Mrows * Dm];
__device__ bf g_Vth[Mrows * Dm], g_Vtl[Mrows * Dm];  // [b][h][d][s]
__device__ bf g_Ctxh[Mrows * Dm], g_Ctxl[Mrows * Dm];

// ===========================================================================
// helpers
// ===========================================================================
__device__ __forceinline__ void mma16816(float* c, const uint32_t* a, uint32_t b0, uint32_t b1)
{
    asm volatile(
        "mma.sync.aligned.m16n8k16.row.col.f32.bf16.bf16.f32 "
        "{%0,%1,%2,%3}, {%4,%5,%6,%7}, {%8,%9}, {%0,%1,%2,%3};\n"
        : "+f"(c[0]), "+f"(c[1]), "+f"(c[2]), "+f"(c[3])
        : "r"(a[0]), "r"(a[1]), "r"(a[2]), "r"(a[3]), "r"(b0), "r"(b1));
}

__device__ __forceinline__ void ldsm4(uint32_t& r0, uint32_t& r1, uint32_t& r2, uint32_t& r3,
                                      uint32_t addr)
{
    asm volatile("ldmatrix.sync.aligned.m8n8.x4.shared.b16 {%0,%1,%2,%3}, [%4];\n"
                 : "=r"(r0), "=r"(r1), "=r"(r2), "=r"(r3) : "r"(addr));
}

__device__ __forceinline__ void split2(float x, float y, uint32_t& hi, uint32_t& lo)
{
    bf hx = __float2bfloat16(x), hy = __float2bfloat16(y);
    bf lx = __float2bfloat16(x - __bfloat162float(hx));
    bf ly = __float2bfloat16(y - __bfloat162float(hy));
    __nv_bfloat162 h(hx, hy), l(lx, ly);
    hi = *(uint32_t*)&h; lo = *(uint32_t*)&l;
}

__device__ __forceinline__ uint32_t smem_u32(const void* p)
{
    uint32_t a;
    asm("{ .reg .u64 t; cvta.to.shared.u64 t, %1; cvt.u32.u64 %0, t; }" : "=r"(a) : "l"(p));
    return a;
}
__device__ __forceinline__ void cp16(uint32_t dst, const void* src)
{
    asm volatile("cp.async.ca.shared.global [%0], [%1], 16;\n" :: "r"(dst), "l"(src));
}
#define CP_COMMIT() asm volatile("cp.async.commit_group;\n" ::: "memory")
#define CP_WAIT(n)  asm volatile("cp.async.wait_group %0;\n" :: "n"(n) : "memory")

// ===========================================================================
// pre-split: fp32 -> bf16 hi/lo
// ===========================================================================
__global__ __launch_bounds__(256)
void split_all(const float* q, const float* k, const float* v,
               const float* wq, const float* wk, const float* wv, const float* wo)
{
    const int z = blockIdx.y;
    const float* src; bf *hi, *lo; int n;
    switch (z) {
        case 0: src = q;  hi = g_xqh; lo = g_xql; n = Mrows * Dm; break;
        case 1: src = k;  hi = g_xkh; lo = g_xkl; n = Mrows * Dm; break;
        case 2: src = v;  hi = g_xvh; lo = g_xvl; n = Mrows * Dm; break;
        case 3: src = wq; hi = g_wqh; lo = g_wql; n = Dm * Dm;    break;
        case 4: src = wk; hi = g_wkh; lo = g_wkl; n = Dm * Dm;    break;
        case 5: src = wv; hi = g_wvh; lo = g_wvl; n = Dm * Dm;    break;
        default: src = wo; hi = g_woh; lo = g_wol; n = Dm * Dm;   break;
    }
    const int t = blockIdx.x * 256 + threadIdx.x;
    if (t * 4 >= n) return;
    const float4 x = ((const float4*)src)[t];
    uint32_t h0, l0, h1, l1;
    split2(x.x, x.y, h0, l0);
    split2(x.z, x.w, h1, l1);
    ((uint2*)hi)[t] = make_uint2(h0, h1);
    ((uint2*)lo)[t] = make_uint2(l0, l1);
}

// ===========================================================================
// Unified tensor-core GEMM (pre-split bf16), ldmatrix fragment loads.
// z: 0=Q  1=K  2=V(transposed out)  3=O(fp32 out)
// ===========================================================================
#define GBK 32
#define GST 40
#define ARR_E (128 * GST)
#define STG_E (4 * ARR_E)
#define STG_B (STG_E * 2)
#define SMEM_TOT (2 * STG_B)   // 81920 B

__global__ __launch_bounds__(256, 2)
void gemm_all(int zbase,
              const float* __restrict__ bq, const float* __restrict__ bk,
              const float* __restrict__ bv, const float* __restrict__ bo,
              float* __restrict__ out)
{
    extern __shared__ bf dsm[];
    const uint32_t sbase = smem_u32(dsm);

    const int z = blockIdx.z + zbase;
    const bf *Ah, *Al, *Wh, *Wl;
    const float* bias;
    bf *Oh = nullptr, *Ol = nullptr;
    float* Cf = nullptr;
    int mode; float qscale = 1.0f;
    switch (z) {
        case 0:  Ah = g_xqh; Al = g_xql; Wh = g_wqh; Wl = g_wql; bias = bq;
                 Oh = g_Qh; Ol = g_Ql; mode = 0; qscale = 0.125f; break;
        case 1:  Ah = g_xkh; Al = g_xkl; Wh = g_wkh; Wl = g_wkl; bias = bk;
                 Oh = g_Kh; Ol = g_Kl; mode = 0; break;
        case 2:  Ah = g_xvh; Al = g_xvl; Wh = g_wvh; Wl = g_wvl; bias = bv;
                 Oh = g_Vth; Ol = g_Vtl; mode = 2; break;
        default: Ah = g_Ctxh; Al = g_Ctxl; Wh = g_woh; Wl = g_wol; bias = bo;
                 Cf = out; mode = 3; break;
    }

    const int tid  = threadIdx.x;
    const int lane = tid & 31;
    const int warp = tid >> 5;
    const int wm   = warp & 3;
    const int wn   = warp >> 2;
    const int gg8  = lane >> 2;
    const int tg   = lane & 3;
    const int bM   = blockIdx.y * 128;
    const int bN   = blockIdx.x * 128;
    const int K    = Dm, N = Dm;

    const int lA_row = (lane & 7) + ((lane >> 3) & 1) * 8;
    const int lA_col = (lane >> 4) * 8;
    const int lB_row = (lane & 7) + (lane >> 4) * 8;
    const int lB_col = ((lane >> 3) & 1) * 8;

    const int lr = tid >> 1;
    const int lq = tid & 1;
    const bf* gA_h = Ah + (size_t)(bM + lr) * K + lq * 16;
    const bf* gA_l = Al + (size_t)(bM + lr) * K + lq * 16;
    const bf* gW_h = Wh + (size_t)(bN + lr) * K + lq * 16;
    const bf* gW_l = Wl + (size_t)(bN + lr) * K + lq * 16;
    const uint32_t drow = lr * (GST * 2) + lq * 32;

    float acc[2][8][4];
    #pragma unroll
    for (int i = 0; i < 2; i++)
        #pragma unroll
        for (int j = 0; j < 8; j++)
            #pragma unroll
            for (int t = 0; t < 4; t++) acc[i][j][t] = 0.f;

    const int nch = K / GBK;   // 32

    {
        const uint32_t d0 = sbase + drow;
        cp16(d0,                  gA_h);
        cp16(d0 + 16,             gA_h + 8);
        cp16(d0 + ARR_E * 2,      gA_l);
        cp16(d0 + ARR_E * 2 + 16, gA_l + 8);
        cp16(d0 + ARR_E * 4,      gW_h);
        cp16(d0 + ARR_E * 4 + 16, gW_h + 8);
        cp16(d0 + ARR_E * 6,      gW_l);
        cp16(d0 + ARR_E * 6 + 16, gW_l + 8);
        CP_COMMIT();
    }

    for (int i = 0; i < nch; i++) {
        if (i + 1 < nch) {
            const int k0 = (i + 1) * GBK;
            const uint32_t d0 = sbase + ((i + 1) & 1) * STG_B + drow;
            cp16(d0,                  gA_h + k0);
            cp16(d0 + 16,             gA_h + k0 + 8);
            cp16(d0 + ARR_E * 2,      gA_l + k0);
            cp16(d0 + ARR_E * 2 + 16, gA_l + k0 + 8);
            cp16(d0 + ARR_E * 4,      gW_h + k0);
            cp16(d0 + ARR_E * 4 + 16, gW_h + k0 + 8);
            cp16(d0 + ARR_E * 6,      gW_l + k0);
            cp16(d0 + ARR_E * 6 + 16, gW_l + k0 + 8);
            CP_COMMIT();
            CP_WAIT(1);
        } else {
            CP_WAIT(0);
        }
        __syncthreads();

        const uint32_t stg = sbase + (i & 1) * STG_B;

        #pragma unroll
        for (int ks = 0; ks < GBK; ks += 16) {
            uint32_t ah[2][4], al[2][4];
            #pragma unroll
            for (int mt = 0; mt < 2; mt++) {
                const uint32_t ra = stg +
                    ((wm * 32 + mt * 16 + lA_row) * GST + ks + lA_col) * 2;
                ldsm4(ah[mt][0], ah[mt][1], ah[mt][2], ah[mt][3], ra);
                ldsm4(al[mt][0], al[mt][1], al[mt][2], al[mt][3], ra + ARR_E * 2);
            }
            #pragma unroll
            for (int np = 0; np < 4; np++) {
                uint32_t bh[4], bl[4];
                const uint32_t rb = stg + ARR_E * 4 +
                    ((wn * 64 + np * 16 + lB_row) * GST + ks + lB_col) * 2;
                ldsm4(bh[0], bh[1], bh[2], bh[3], rb);
                ldsm4(bl[0], bl[1], bl[2], bl[3], rb + ARR_E * 2);
                #pragma unroll
                for (int qq = 0; qq < 2; qq++) {
                    const int nt = np * 2 + qq;
                    #pragma unroll
                    for (int mt = 0; mt < 2; mt++) {
                        mma16816(acc[mt][nt], ah[mt], bh[2 * qq], bh[2 * qq + 1]);
                        mma16816(acc[mt][nt], ah[mt], bl[2 * qq], bl[2 * qq + 1]);
                        mma16816(acc[mt][nt], al[mt], bh[2 * qq], bh[2 * qq + 1]);
                    }
                }
            }
        }
        __syncthreads();
    }

    // ---- epilogue ----
    #pragma unroll
    for (int mt = 0; mt < 2; mt++) {
        #pragma unroll
        for (int nt = 0; nt < 8; nt++) {
            const int col = bN + wn * 64 + nt * 8 + 2 * tg;
            const float b0 = bias[col], b1 = bias[col + 1];
            const int r0 = bM + wm * 32 + mt * 16 + gg8;
            float v00 = acc[mt][nt][0] + b0, v01 = acc[mt][nt][1] + b1;
            float v10 = acc[mt][nt][2] + b0, v11 = acc[mt][nt][3] + b1;
            if (mode == 3) {
                *(float2*)&Cf[(size_t)r0 * N + col]       = make_float2(v00, v01);
                *(float2*)&Cf[(size_t)(r0 + 8) * N + col] = make_float2(v10, v11);
            } else if (mode == 0) {
                v00 *= qscale; v01 *= qscale; v10 *= qscale; v11 *= qscale;
                uint32_t h, l;
                split2(v00, v01, h, l);
                *(uint32_t*)&Oh[(size_t)r0 * N + col] = h;
                *(uint32_t*)&Ol[(size_t)r0 * N + col] = l;
                split2(v10, v11, h, l);
                *(uint32_t*)&Oh[(size_t)(r0 + 8) * N + col] = h;
                *(uint32_t*)&Ol[(size_t)(r0 + 8) * N + col] = l;
            } else { // mode 2: transposed per head [b][h][d][s]
                #pragma unroll
                for (int rr = 0; rr < 2; rr++) {
                    const int r  = r0 + rr * 8;
                    const int bb = r >> 11;
                    const int s  = r & 2047;
                    const float x0 = rr ? v10 : v00;
                    const float x1 = rr ? v11 : v01;
                    #pragma unroll
                    for (int cc = 0; cc < 2; cc++) {
                        const int c  = col + cc;
                        const int hh = c >> 6;
                        const int d  = c & 63;
                        const float x = cc ? x1 : x0;
                        const size_t idx = (((size_t)bb * Hh + hh) * DKh + d) * Sseq + s;
                        bf hi = __float2bfloat16(x);
                        bf lo = __float2bfloat16(x - __bfloat162float(hi));
                        Oh[idx] = hi;
                        Ol[idx] = lo;
                    }
                }
            }
        }
    }
}

// ===========================================================================
// Tensor-core flash attention: ldmatrix fragments + cp.async 2-stage
// double-buffered K/V tiles (loads of tile i+2 overlap compute of tile i+1).
// Dynamic smem: 2 stages x 4 arrays x 64 rows x ALD(=72) bf16 = 73728 B.
// ===========================================================================
#define ALD 72
#define AARR_B 9216                 // 64 * 72 * 2 bytes
#define ASTG_B (4 * AARR_B)         // 36864
#define ASMEM  (2 * ASTG_B)         // 73728

__global__ __launch_bounds__(128, 3)
void attn_tc()
{
    extern __shared__ bf adsm[];
    const uint32_t smb = smem_u32(adsm);

    const int tid  = threadIdx.x;
    const int lane = tid & 31;
    const int warp = tid >> 5;
    const int g    = lane >> 2;
    const int tg   = lane & 3;
    const int b    = blockIdx.z;
    const int h    = blockIdx.y;
    const int q0   = blockIdx.x * 64;

    const int lB_row = (lane & 7) + (lane >> 4) * 8;
    const int lB_col = ((lane >> 3) & 1) * 8;

    uint32_t qh[4][4], ql[4][4];
    {
        const bf* Qh = g_Qh + (size_t)(b * Sseq + q0 + warp * 16) * Dm + h * DKh;
        const bf* Ql = g_Ql + (size_t)(b * Sseq + q0 + warp * 16) * Dm + h * DKh;
        #pragma unroll
        for (int ks = 0; ks < 4; ks++) {
            const int c0 = ks * 16 + 2 * tg;
            qh[ks][0] = *(const uint32_t*)&Qh[(size_t)g * Dm + c0];
            qh[ks][1] = *(const uint32_t*)&Qh[(size_t)(g + 8) * Dm + c0];
            qh[ks][2] = *(const uint32_t*)&Qh[(size_t)g * Dm + c0 + 8];
            qh[ks][3] = *(const uint32_t*)&Qh[(size_t)(g + 8) * Dm + c0 + 8];
            ql[ks][0] = *(const uint32_t*)&Ql[(size_t)g * Dm + c0];
            ql[ks][1] = *(const uint32_t*)&Ql[(size_t)(g + 8) * Dm + c0];
            ql[ks][2] = *(const uint32_t*)&Ql[(size_t)g * Dm + c0 + 8];
            ql[ks][3] = *(const uint32_t*)&Ql[(size_t)(g + 8) * Dm + c0 + 8];
        }
    }

    float o[8][4];
    #pragma unroll
    for (int nt = 0; nt < 8; nt++)
        #pragma unroll
        for (int t = 0; t < 4; t++) o[nt][t] = 0.f;
    float m0 = -1e30f, m1 = -1e30f, l0 = 0.f, l1 = 0.f;

    const bf* Kbh = g_Kh + (size_t)b * Sseq * Dm + h * DKh;
    const bf* Kbl = g_Kl + (size_t)b * Sseq * Dm + h * DKh;
    const bf* Vbh = g_Vth + ((size_t)b * Hh + h) * DKh * Sseq;
    const bf* Vbl = g_Vtl + ((size_t)b * Hh + h) * DKh * Sseq;

    // cooperative tile load into stage st (64 keys starting at ti*64)
    #define LOAD_KV(ti, st)                                                      \
        {                                                                        \
            const int kv = (ti) * 64;                                            \
            const uint32_t db = smb + (uint32_t)(st) * ASTG_B;                   \
            _Pragma("unroll")                                                    \
            for (int jj = 0; jj < 4; jj++) {                                     \
                const int idx = tid + jj * 128;                                  \
                const int r = idx >> 3, cq = idx & 7;                            \
                const uint32_t off = (uint32_t)(r * (ALD * 2) + cq * 16);        \
                cp16(db + off,              Kbh + (size_t)(kv + r) * Dm + cq * 8);\
                cp16(db + AARR_B + off,     Kbl + (size_t)(kv + r) * Dm + cq * 8);\
                cp16(db + 2 * AARR_B + off, Vbh + (size_t)r * Sseq + kv + cq * 8);\
                cp16(db + 3 * AARR_B + off, Vbl + (size_t)r * Sseq + kv + cq * 8);\
            }                                                                    \
            CP_COMMIT();                                                         \
        }

    LOAD_KV(0, 0);
    LOAD_KV(1, 1);

    const int ntiles = Sseq / 64;   // 32
    for (int i = 0; i < ntiles; i++) {
        const int st = i & 1;
        if (i == ntiles - 1) { CP_WAIT(0); } else { CP_WAIT(1); }
        __syncthreads();

        const uint32_t kh_base = smb + (uint32_t)st * ASTG_B;
        const uint32_t kl_base = kh_base + AARR_B;
        const uint32_t vh_base = kh_base + 2 * AARR_B;
        const uint32_t vl_base = kh_base + 3 * AARR_B;

        // ---- S = Q K^T ----
        float s[8][4];
        #pragma unroll
        for (int nt = 0; nt < 8; nt++)
            #pragma unroll
            for (int t = 0; t < 4; t++) s[nt][t] = 0.f;
        #pragma unroll
        for (int ks = 0; ks < 4; ks++) {
            const uint32_t coff = ((uint32_t)(ks * 16 + lB_col)) * 2;
            #pragma unroll
            for (int np = 0; np < 4; np++) {
                uint32_t bh[4], bl[4];
                const uint32_t roff = (uint32_t)((np * 16 + lB_row) * ALD) * 2 + coff;
                ldsm4(bh[0], bh[1], bh[2], bh[3], kh_base + roff);
                ldsm4(bl[0], bl[1], bl[2], bl[3], kl_base + roff);
                #pragma unroll
                for (int qq = 0; qq < 2; qq++) {
                    const int nt = np * 2 + qq;
                    mma16816(s[nt], qh[ks], bh[2 * qq], bh[2 * qq + 1]);
                    mma16816(s[nt], qh[ks], bl[2 * qq], bl[2 * qq + 1]);
                    mma16816(s[nt], ql[ks], bh[2 * qq], bh[2 * qq + 1]);
                }
            }
        }

        // ---- online softmax ----
        float mx0 = -1e30f, mx1 = -1e30f;
        #pragma unroll
        for (int nt = 0; nt < 8; nt++) {
            mx0 = fmaxf(mx0, fmaxf(s[nt][0], s[nt][1]));
            mx1 = fmaxf(mx1, fmaxf(s[nt][2], s[nt][3]));
        }
        mx0 = fmaxf(mx0, __shfl_xor_sync(0xffffffffu, mx0, 1));
        mx0 = fmaxf(mx0, __shfl_xor_sync(0xffffffffu, mx0, 2));
        mx1 = fmaxf(mx1, __shfl_xor_sync(0xffffffffu, mx1, 1));
        mx1 = fmaxf(mx1, __shfl_xor_sync(0xffffffffu, mx1, 2));
        const float nm0 = fmaxf(m0, mx0), nm1 = fmaxf(m1, mx1);
        const float sc0 = __expf(m0 - nm0), sc1 = __expf(m1 - nm1);
        m0 = nm0; m1 = nm1;
        l0 *= sc0; l1 *= sc1;
        #pragma unroll
        for (int nt = 0; nt < 8; nt++) {
            o[nt][0] *= sc0; o[nt][1] *= sc0;
            o[nt][2] *= sc1; o[nt][3] *= sc1;
        }

        // ---- P = exp(S - m); PV ----
        #pragma unroll
        for (int ks = 0; ks < 4; ks++) {
            const float e00 = __expf(s[2 * ks][0] - nm0);
            const float e01 = __expf(s[2 * ks][1] - nm0);
            const float e10 = __expf(s[2 * ks][2] - nm1);
            const float e11 = __expf(s[2 * ks][3] - nm1);
            const float f00 = __expf(s[2 * ks + 1][0] - nm0);
            const float f01 = __expf(s[2 * ks + 1][1] - nm0);
            const float f10 = __expf(s[2 * ks + 1][2] - nm1);
            const float f11 = __expf(s[2 * ks + 1][3] - nm1);
            l0 += (e00 + e01) + (f00 + f01);
            l1 += (e10 + e11) + (f10 + f11);
            uint32_t ph[4], pl[4];
            split2(e00, e01, ph[0], pl[0]);
            split2(e10, e11, ph[1], pl[1]);
            split2(f00, f01, ph[2], pl[2]);
            split2(f10, f11, ph[3], pl[3]);
            const uint32_t coff = ((uint32_t)(ks * 16 + lB_col)) * 2;
            #pragma unroll
            for (int np = 0; np < 4; np++) {
                uint32_t bh[4], bl[4];
                const uint32_t roff = (uint32_t)((np * 16 + lB_row) * ALD) * 2 + coff;
                ldsm4(bh[0], bh[1], bh[2], bh[3], vh_base + roff);
                ldsm4(bl[0], bl[1], bl[2], bl[3], vl_base + roff);
                #pragma unroll
                for (int qq = 0; qq < 2; qq++) {
                    const int nt = np * 2 + qq;
                    mma16816(o[nt], ph, bh[2 * qq], bh[2 * qq + 1]);
                    mma16816(o[nt], ph, bl[2 * qq], bl[2 * qq + 1]);
                    mma16816(o[nt], pl, bh[2 * qq], bh[2 * qq + 1]);
                }
            }
        }

        __syncthreads();                    // everyone done reading stage st
        if (i + 2 < ntiles) LOAD_KV(i + 2, st);
    }
    #undef LOAD_KV

    l0 += __shfl_xor_sync(0xffffffffu, l0, 1);
    l0 += __shfl_xor_sync(0xffffffffu, l0, 2);
    l1 += __shfl_xor_sync(0xffffffffu, l1, 1);
    l1 += __shfl_xor_sync(0xffffffffu, l1, 2);
    const float i0 = 1.f / l0, i1 = 1.f / l1;

    bf* OpH = g_Ctxh + (size_t)(b * Sseq + q0 + warp * 16) * Dm + h * DKh;
    bf* OpL = g_Ctxl + (size_t)(b * Sseq + q0 + warp * 16) * Dm + h * DKh;
    #pragma unroll
    for (int nt = 0; nt < 8; nt++) {
        const int c = nt * 8 + 2 * tg;
        uint32_t h0, l0w, h1, l1w;
        split2(o[nt][0] * i0, o[nt][1] * i0, h0, l0w);
        split2(o[nt][2] * i1, o[nt][3] * i1, h1, l1w);
        *(uint32_t*)&OpH[(size_t)g * Dm + c]       = h0;
        *(uint32_t*)&OpL[(size_t)g * Dm + c]       = l0w;
        *(uint32_t*)&OpH[(size_t)(g + 8) * Dm + c] = h1;
        *(uint32_t*)&OpL[(size_t)(g + 8) * Dm + c] = l1w;
    }
}

// ---------------------------------------------------------------------------
// Launch
// ---------------------------------------------------------------------------
extern "C" void kernel_launch(void* const* d_in, const int* in_sizes, int n_in,
                              void* d_out, int out_size)
{
    const float* q  = (const float*)d_in[0];
    const float* k  = (const float*)d_in[1];
    const float* v  = (const float*)d_in[2];
    const float* wq = (const float*)d_in[3];
    const float* bq = (const float*)d_in[4];
    const float* wk = (const float*)d_in[5];
    const float* bk = (const float*)d_in[6];
    const float* wv = (const float*)d_in[7];
    const float* bv = (const float*)d_in[8];
    const float* wo = (const float*)d_in[9];
    const float* bo = (const float*)d_in[10];
    float* out = (float*)d_out;

    cudaFuncSetAttribute(gemm_all, cudaFuncAttributeMaxDynamicSharedMemorySize, SMEM_TOT);
    cudaFuncSetAttribute(attn_tc,  cudaFuncAttributeMaxDynamicSharedMemorySize, ASMEM);

    split_all<<<dim3((Mrows * Dm) / (4 * 256), 7), 256>>>(q, k, v, wq, wk, wv, wo);

    gemm_all<<<dim3(Dm / 128, Mrows / 128, 3), 256, SMEM_TOT>>>(0, bq, bk, bv, bo, out);

    attn_tc<<<dim3(Sseq / 64, Hh, Bsz), 128, ASMEM>>>();

    gemm_all<<<dim3(Dm / 128, Mrows / 128, 1), 256, SMEM_TOT>>>(3, bq, bk, bv, bo, out);
}